// round 13
// baseline (speedup 1.0000x reference)
#include <cuda_runtime.h>
#include <cuda_bf16.h>

#define CCH 256        // channels
#define LV 2           // levels
#define NP 4           // points
#define NOFF 16        // offset outputs (LV*NP*2)
#define NAW 8          // attn outputs (LV*NP)
#define NOUT 24        // total projection outputs
#define NKT 32         // k-tiles (256 / 8)
#define QPB 64         // queries per block
#define WPAD 26        // padded row stride for weight smem (bank-exact)

__device__ __forceinline__ unsigned f2tf32(float f) {
    unsigned r;
    asm("cvt.rna.tf32.f32 %0, %1;" : "=r"(r) : "f"(f));
    return r;
}

__device__ __forceinline__ void mma_tf32(float d[4],
                                         unsigned a0, unsigned a1,
                                         unsigned a2, unsigned a3,
                                         unsigned b0, unsigned b1) {
    asm("mma.sync.aligned.m16n8k8.row.col.f32.tf32.tf32.f32 "
        "{%0,%1,%2,%3}, {%4,%5,%6,%7}, {%8,%9}, {%0,%1,%2,%3};"
        : "+f"(d[0]), "+f"(d[1]), "+f"(d[2]), "+f"(d[3])
        : "r"(a0), "r"(a1), "r"(a2), "r"(a3), "r"(b0), "r"(b1));
}

// ---------------------------------------------------------------------------
// Fused kernel: block = 64 queries.
//  Phase A: coalesced-stage W (tf32) into pad-26 smem.
//  Phase B: warps 0-3 run tf32 MMA projection (16 queries each) + softmax,
//           params land in smem (no global round trip).
//  Phase C: all 8 warps sample 8 queries each (tent-weight dedup, merged
//           levels, 4-cell batched gathers).
// Proj (tensor+DRAM) and sample (L2+LSU) phases of different resident blocks
// overlap on the SM.
// ---------------------------------------------------------------------------
__global__ __launch_bounds__(256)
void fused_kernel(const float* __restrict__ query,
                  const float* __restrict__ value,
                  const float* __restrict__ refpts,
                  const int*   __restrict__ shapes_raw,
                  const float* __restrict__ W_off,  const float* __restrict__ b_off,
                  const float* __restrict__ W_attn, const float* __restrict__ b_attn,
                  float* __restrict__ out, int Q)
{
    __shared__ unsigned wsm[CCH * WPAD];   // 26.6KB  tf32 weights, [k][n] pad-26
    __shared__ float    pq[QPB][25];       // 6.25KB  per-query params

    const int tid  = threadIdx.x;
    const int lane = tid & 31;
    const int warp = tid >> 5;

    // ---- Phase A: stage weights, fully coalesced global reads ----
    for (int i = tid; i < CCH * NOFF; i += 256) {
        const int k = i >> 4, n = i & 15;
        wsm[k * WPAD + n] = f2tf32(__ldg(W_off + i));
    }
    for (int i = tid; i < CCH * NAW; i += 256) {
        const int k = i >> 3, n = i & 7;
        wsm[k * WPAD + NOFF + n] = f2tf32(__ldg(W_attn + i));
    }
    __syncthreads();

    // ---- Phase B: projection (warps 0-3) ----
    if (warp < 4) {
        const int gid = lane >> 2;      // row within 8
        const int tig = lane & 3;       // thread-in-group

        const int qbase = blockIdx.x * QPB + warp * 16;
        const int qr0 = min(qbase + gid,     Q - 1);
        const int qr1 = min(qbase + gid + 8, Q - 1);
        const float4* q0p = (const float4*)(query + (size_t)qr0 * CCH) + tig;
        const float4* q1p = (const float4*)(query + (size_t)qr1 * CCH) + tig;

        // lane-invariant part of the B index: bank = C + 8*tig + gid (all 32)
        const unsigned* wl = wsm + 104 * tig + gid;

        float d[3][4];
#pragma unroll
        for (int nt = 0; nt < 3; nt++)
#pragma unroll
            for (int i = 0; i < 4; i++) d[nt][i] = 0.f;

        float4 r0lo = __ldg(q0p);
        float4 r0hi = __ldg(q0p + 4);
        float4 r1lo = __ldg(q1p);
        float4 r1hi = __ldg(q1p + 4);

#pragma unroll
        for (int kt4 = 0; kt4 < NKT / 4; kt4++) {
            float4 n0lo, n0hi, n1lo, n1hi;
            if (kt4 < NKT / 4 - 1) {
                n0lo = __ldg(q0p + (kt4 + 1) * 8);
                n0hi = __ldg(q0p + (kt4 + 1) * 8 + 4);
                n1lo = __ldg(q1p + (kt4 + 1) * 8);
                n1hi = __ldg(q1p + (kt4 + 1) * 8 + 4);
            }
            const int kb = 832 * kt4;   // 32*WPAD per k-group

#define PSTEP(I, C)                                                            \
            do {                                                               \
                const unsigned a0 = f2tf32(r0lo.C);                            \
                const unsigned a1 = f2tf32(r1lo.C);                            \
                const unsigned a2 = f2tf32(r0hi.C);                            \
                const unsigned a3 = f2tf32(r1hi.C);                            \
                const int bb = kb + WPAD * I;                                  \
                mma_tf32(d[0], a0, a1, a2, a3, wl[bb],      wl[bb + 416]);     \
                mma_tf32(d[1], a0, a1, a2, a3, wl[bb + 8],  wl[bb + 424]);     \
                mma_tf32(d[2], a0, a1, a2, a3, wl[bb + 16], wl[bb + 432]);     \
            } while (0)

            PSTEP(0, x);
            PSTEP(1, y);
            PSTEP(2, z);
            PSTEP(3, w);
#undef PSTEP

            if (kt4 < NKT / 4 - 1) {
                r0lo = n0lo; r0hi = n0hi; r1lo = n1lo; r1hi = n1hi;
            }
        }

        // scatter fragments into pq rows
#pragma unroll
        for (int nt = 0; nt < 3; nt++) {
            const int col = nt * 8 + 2 * tig;
            pq[warp * 16 + gid][col]         = d[nt][0];
            pq[warp * 16 + gid][col + 1]     = d[nt][1];
            pq[warp * 16 + gid + 8][col]     = d[nt][2];
            pq[warp * 16 + gid + 8][col + 1] = d[nt][3];
        }
        __syncwarp();

        if (lane < 16) {
            float p[NOUT];
#pragma unroll
            for (int j = 0; j < NOUT; j++) p[j] = pq[warp * 16 + lane][j];
#pragma unroll
            for (int j = 0; j < NOFF; j++) p[j] += __ldg(b_off + j);
#pragma unroll
            for (int j = 0; j < NAW; j++)  p[NOFF + j] += __ldg(b_attn + j);

            float m = p[NOFF];
#pragma unroll
            for (int j = 1; j < NAW; j++) m = fmaxf(m, p[NOFF + j]);
            float s = 0.f;
#pragma unroll
            for (int j = 0; j < NAW; j++) {
                const float e = __expf(p[NOFF + j] - m);
                p[NOFF + j] = e;
                s += e;
            }
            const float inv = 1.f / s;
#pragma unroll
            for (int j = 0; j < NAW; j++) p[NOFF + j] *= inv;
#pragma unroll
            for (int j = 0; j < NOUT; j++) pq[warp * 16 + lane][j] = p[j];
        }
    }
    __syncthreads();

    // ---- Phase C: sampling, 8 queries per warp ----
    int HH[LV], WW[LV];
    {
        const int st = (__ldg(shapes_raw + 1) == 0) ? 2 : 1;
#pragma unroll
        for (int l = 0; l < LV; l++) {
            HH[l] = __ldg(shapes_raw + (2 * l) * st);
            WW[l] = __ldg(shapes_raw + (2 * l + 1) * st);
        }
    }
    const float4* vb4 = (const float4*)value;
    const int mylevel = lane >> 4;
    const int mycell  = lane & 15;

    for (int it = 0; it < 8; it++) {
        const int qloc = warp * 8 + it;
        const int q = blockIdx.x * QPB + qloc;
        if (q >= Q) break;

        const float* pp  = &pq[qloc][0];
        const float* ref = refpts + (size_t)q * (LV * 2);

        float4 acc0 = make_float4(0.f, 0.f, 0.f, 0.f);
        float4 acc1 = make_float4(0.f, 0.f, 0.f, 0.f);

        float    myw   = 0.f;
        unsigned myoff = 0;
        unsigned loff4 = 0;

#define GATHER_NOW(OFF4, W)                                                    \
        do {                                                                   \
            const float4 v0 = __ldg(vb4 + (OFF4) + lane);                      \
            const float4 v1 = __ldg(vb4 + (OFF4) + 32 + lane);                 \
            acc0.x = fmaf((W), v0.x, acc0.x);                                  \
            acc0.y = fmaf((W), v0.y, acc0.y);                                  \
            acc0.z = fmaf((W), v0.z, acc0.z);                                  \
            acc0.w = fmaf((W), v0.w, acc0.w);                                  \
            acc1.x = fmaf((W), v1.x, acc1.x);                                  \
            acc1.y = fmaf((W), v1.y, acc1.y);                                  \
            acc1.z = fmaf((W), v1.z, acc1.z);                                  \
            acc1.w = fmaf((W), v1.w, acc1.w);                                  \
        } while (0)

#pragma unroll
        for (int l = 0; l < LV; l++) {
            const int Hs = HH[l], Ws = WW[l];
            const float bx = __ldg(ref + 2 * l)     * (float)Ws - 0.5f;
            const float by = __ldg(ref + 2 * l + 1) * (float)Hs - 0.5f;

            const float ixs[NP] = {bx + pp[l * 8 + 0], bx + pp[l * 8 + 2],
                                   bx + pp[l * 8 + 4], bx + pp[l * 8 + 6]};
            const float iys[NP] = {by + pp[l * 8 + 1], by + pp[l * 8 + 3],
                                   by + pp[l * 8 + 5], by + pp[l * 8 + 7]};
            const float aws[NP] = {pp[16 + l * 4], pp[17 + l * 4],
                                   pp[18 + l * 4], pp[19 + l * 4]};

            int x0[NP], y0[NP];
#pragma unroll
            for (int pt = 0; pt < NP; pt++) {
                x0[pt] = (int)floorf(ixs[pt]);
                y0[pt] = (int)floorf(iys[pt]);
            }

            const int xmin = min(min(x0[0], x0[1]), min(x0[2], x0[3]));
            const int ymin = min(min(y0[0], y0[1]), min(y0[2], y0[3]));
            const int xmax = max(max(x0[0], x0[1]), max(x0[2], x0[3]));
            const int ymax = max(max(y0[0], y0[1]), max(y0[2], y0[3]));

            if (xmax - xmin <= 2 && ymax - ymin <= 2) {
                if (mylevel == l) {
                    const int xx = xmin + (mycell & 3);
                    const int yy = ymin + (mycell >> 2);
                    const float Xc = (float)xx;
                    const float Yc = (float)yy;
                    float w = 0.f;
#pragma unroll
                    for (int pt = 0; pt < NP; pt++) {
                        const float wx = fmaxf(0.f, 1.f - fabsf(ixs[pt] - Xc));
                        const float wy = fmaxf(0.f, 1.f - fabsf(iys[pt] - Yc));
                        w = fmaf(aws[pt] * wx, wy, w);
                    }
                    const bool ok = (unsigned)xx < (unsigned)Ws &&
                                    (unsigned)yy < (unsigned)Hs;
                    myw = ok ? w : 0.f;
                    const int xc = min(max(xx, 0), Ws - 1);
                    const int yc = min(max(yy, 0), Hs - 1);
                    myoff = loff4 + (((unsigned)(yc * Ws + xc)) << 6);
                }
            } else {
                // Rare fallback: immediate per-corner gathers.
#pragma unroll
                for (int pt = 0; pt < NP; pt++) {
                    const float x0f = floorf(ixs[pt]);
                    const float y0f = floorf(iys[pt]);
                    const float fx = ixs[pt] - x0f;
                    const float fy = iys[pt] - y0f;
                    const float a  = aws[pt];
                    const float cw[4] = {(1.f - fx) * (1.f - fy) * a,
                                         fx * (1.f - fy) * a,
                                         (1.f - fx) * fy * a,
                                         fx * fy * a};
                    const int xs[2] = {x0[pt], x0[pt] + 1};
                    const int ys[2] = {y0[pt], y0[pt] + 1};
#pragma unroll
                    for (int cy = 0; cy < 2; cy++) {
#pragma unroll
                        for (int cx = 0; cx < 2; cx++) {
                            const int xx = xs[cx];
                            const int yy = ys[cy];
                            const float w = cw[cy * 2 + cx];
                            if ((unsigned)xx < (unsigned)Ws &&
                                (unsigned)yy < (unsigned)Hs) {
                                const unsigned off4 =
                                    loff4 + (((unsigned)(yy * Ws + xx)) << 6);
                                GATHER_NOW(off4, w);
                            }
                        }
                    }
                }
            }
            loff4 += (unsigned)(Hs * Ws) * 64u;
        }

        // Merged gather loop: 4 cells per iteration, loads batched.
        unsigned nz = __ballot_sync(0xffffffffu, myw != 0.f);
        while (nz) {
            int c0 = __ffs(nz) - 1; nz &= nz - 1;
            int c1 = __ffs(nz) - 1; nz &= nz - 1;
            int c2 = __ffs(nz) - 1; nz &= nz - 1;
            int c3 = __ffs(nz) - 1; nz &= nz - 1;

            float    w0 = __shfl_sync(0xffffffffu, myw,   c0 & 31);
            unsigned f0 = __shfl_sync(0xffffffffu, myoff, c0 & 31);
            float    w1 = __shfl_sync(0xffffffffu, myw,   c1 & 31);
            unsigned f1 = __shfl_sync(0xffffffffu, myoff, c1 & 31);
            float    w2 = __shfl_sync(0xffffffffu, myw,   c2 & 31);
            unsigned f2 = __shfl_sync(0xffffffffu, myoff, c2 & 31);
            float    w3 = __shfl_sync(0xffffffffu, myw,   c3 & 31);
            unsigned f3 = __shfl_sync(0xffffffffu, myoff, c3 & 31);
            if (c1 < 0) w1 = 0.f;
            if (c2 < 0) w2 = 0.f;
            if (c3 < 0) w3 = 0.f;

            float4 a0 = make_float4(0.f,0.f,0.f,0.f), b0 = a0;
            float4 a1 = a0, b1 = a0, a2 = a0, b2 = a0, a3 = a0, b3 = a0;
            a0 = __ldg(vb4 + f0 + lane);
            b0 = __ldg(vb4 + f0 + 32 + lane);
            if (c1 >= 0) { a1 = __ldg(vb4 + f1 + lane); b1 = __ldg(vb4 + f1 + 32 + lane); }
            if (c2 >= 0) { a2 = __ldg(vb4 + f2 + lane); b2 = __ldg(vb4 + f2 + 32 + lane); }
            if (c3 >= 0) { a3 = __ldg(vb4 + f3 + lane); b3 = __ldg(vb4 + f3 + 32 + lane); }

            acc0.x = fmaf(w0, a0.x, acc0.x); acc0.y = fmaf(w0, a0.y, acc0.y);
            acc0.z = fmaf(w0, a0.z, acc0.z); acc0.w = fmaf(w0, a0.w, acc0.w);
            acc1.x = fmaf(w0, b0.x, acc1.x); acc1.y = fmaf(w0, b0.y, acc1.y);
            acc1.z = fmaf(w0, b0.z, acc1.z); acc1.w = fmaf(w0, b0.w, acc1.w);

            acc0.x = fmaf(w1, a1.x, acc0.x); acc0.y = fmaf(w1, a1.y, acc0.y);
            acc0.z = fmaf(w1, a1.z, acc0.z); acc0.w = fmaf(w1, a1.w, acc0.w);
            acc1.x = fmaf(w1, b1.x, acc1.x); acc1.y = fmaf(w1, b1.y, acc1.y);
            acc1.z = fmaf(w1, b1.z, acc1.z); acc1.w = fmaf(w1, b1.w, acc1.w);

            acc0.x = fmaf(w2, a2.x, acc0.x); acc0.y = fmaf(w2, a2.y, acc0.y);
            acc0.z = fmaf(w2, a2.z, acc0.z); acc0.w = fmaf(w2, a2.w, acc0.w);
            acc1.x = fmaf(w2, b2.x, acc1.x); acc1.y = fmaf(w2, b2.y, acc1.y);
            acc1.z = fmaf(w2, b2.z, acc1.z); acc1.w = fmaf(w2, b2.w, acc1.w);

            acc0.x = fmaf(w3, a3.x, acc0.x); acc0.y = fmaf(w3, a3.y, acc0.y);
            acc0.z = fmaf(w3, a3.z, acc0.z); acc0.w = fmaf(w3, a3.w, acc0.w);
            acc1.x = fmaf(w3, b3.x, acc1.x); acc1.y = fmaf(w3, b3.y, acc1.y);
            acc1.z = fmaf(w3, b3.z, acc1.z); acc1.w = fmaf(w3, b3.w, acc1.w);
        }
#undef GATHER_NOW

        float4* op = (float4*)(out + (size_t)q * CCH);
        op[lane]      = acc0;   // channels [4*lane, 4*lane+4)
        op[32 + lane] = acc1;   // channels [128+4*lane, ...)
    }
}

extern "C" void kernel_launch(void* const* d_in, const int* in_sizes, int n_in,
                              void* d_out, int out_size)
{
    const float* query   = (const float*)d_in[0];
    // d_in[1] = key (unused)
    const float* value   = (const float*)d_in[2];
    const float* refpts  = (const float*)d_in[3];
    const int*   shapes  = (const int*)d_in[4];
    const float* W_off   = (const float*)d_in[5];
    const float* b_off   = (const float*)d_in[6];
    const float* W_attn  = (const float*)d_in[7];
    const float* b_attn  = (const float*)d_in[8];
    float*       out     = (float*)d_out;

    const int Q = in_sizes[0] / CCH;

    fused_kernel<<<(Q + QPB - 1) / QPB, 256>>>(
        query, value, refpts, shapes, W_off, b_off, W_attn, b_attn, out, Q);
}

// round 14
// speedup vs baseline: 1.3449x; 1.3449x over previous
#include <cuda_runtime.h>
#include <cuda_bf16.h>

#define CCH 256        // channels
#define LV 2           // levels
#define NP 4           // points
#define NOFF 16        // offset outputs (LV*NP*2)
#define NAW 8          // attn outputs (LV*NP)
#define NOUT 24        // total projection outputs
#define WPB 8          // warps per block (sampling kernel)
#define NKT 32         // k-tiles (256 / 8)
#define NNT 3          // n-tiles (24 / 8)
#define K1_WARPS 4     // proj warps per block (64 queries/block)

// Scratch: per-query params {16 pre-added pixel coords, 8 normalized attn w}.
__device__ float g_P[1 << 21];   // 8.4 MB

__device__ __forceinline__ unsigned f2tf32(float f) {
    unsigned r;
    asm("cvt.rna.tf32.f32 %0, %1;" : "=r"(r) : "f"(f));
    return r;
}

__device__ __forceinline__ void mma_tf32(float d[4],
                                         unsigned a0, unsigned a1,
                                         unsigned a2, unsigned a3,
                                         unsigned b0, unsigned b1) {
    asm("mma.sync.aligned.m16n8k8.row.col.f32.tf32.tf32.f32 "
        "{%0,%1,%2,%3}, {%4,%5,%6,%7}, {%8,%9}, {%0,%1,%2,%3};"
        : "+f"(d[0]), "+f"(d[1]), "+f"(d[2]), "+f"(d[3])
        : "r"(a0), "r"(a1), "r"(a2), "r"(a3), "r"(b0), "r"(b1));
}

// ---------------------------------------------------------------------------
// Kernel 1: projection + softmax via tf32 MMA (R10/R12 structure, proven).
// Epilogue folds reference points: stores ix/iy pixel coords directly.
// ---------------------------------------------------------------------------
__global__ __launch_bounds__(K1_WARPS * 32)
void proj_kernel(const float* __restrict__ query,
                 const float* __restrict__ refpts,
                 const int*   __restrict__ shapes_raw,
                 const float* __restrict__ W_off,  const float* __restrict__ b_off,
                 const float* __restrict__ W_attn, const float* __restrict__ b_attn,
                 int Q)
{
    __shared__ unsigned b0sm[NKT * NNT * 32];     // 12KB
    __shared__ unsigned b1sm[NKT * NNT * 32];     // 12KB
    __shared__ float    csm[K1_WARPS][16][28];    // 7KB epilogue staging

    for (int idx = threadIdx.x; idx < NKT * NNT * 32; idx += K1_WARPS * 32) {
        const int ln   = idx & 31;
        const int pair = idx >> 5;
        const int kt   = pair / 3;
        const int nt   = pair - kt * 3;
        const int tig  = ln & 3;
        const int gid  = ln >> 2;
        const int n    = nt * 8 + gid;
        const int k0   = 32 * (kt >> 2) + 4 * tig + (kt & 3);
        const int k1   = k0 + 16;
        float w0, w1;
        if (n < NOFF) {
            w0 = __ldg(W_off + k0 * NOFF + n);
            w1 = __ldg(W_off + k1 * NOFF + n);
        } else {
            w0 = __ldg(W_attn + k0 * NAW + (n - NOFF));
            w1 = __ldg(W_attn + k1 * NAW + (n - NOFF));
        }
        b0sm[idx] = f2tf32(w0);
        b1sm[idx] = f2tf32(w1);
    }
    __syncthreads();

    const int tid  = threadIdx.x;
    const int lane = tid & 31;
    const int warp = tid >> 5;
    const int gid  = lane >> 2;
    const int tig  = lane & 3;

    const int qbase = blockIdx.x * (K1_WARPS * 16) + warp * 16;
    const int qr0 = min(qbase + gid,     Q - 1);
    const int qr1 = min(qbase + gid + 8, Q - 1);
    const float4* q0p = (const float4*)(query + (size_t)qr0 * CCH) + tig;
    const float4* q1p = (const float4*)(query + (size_t)qr1 * CCH) + tig;

    float d[NNT][4];
#pragma unroll
    for (int nt = 0; nt < NNT; nt++)
#pragma unroll
        for (int i = 0; i < 4; i++) d[nt][i] = 0.f;

#pragma unroll
    for (int kt4 = 0; kt4 < NKT / 4; kt4++) {
        const float4 r0lo = __ldg(q0p + kt4 * 8);
        const float4 r0hi = __ldg(q0p + kt4 * 8 + 4);
        const float4 r1lo = __ldg(q1p + kt4 * 8);
        const float4 r1hi = __ldg(q1p + kt4 * 8 + 4);
        const int base = (kt4 * 4) * (NNT * 32) + lane;

#define PSTEP(I, C)                                                            \
        do {                                                                   \
            const unsigned a0 = f2tf32(r0lo.C);                                \
            const unsigned a1 = f2tf32(r1lo.C);                                \
            const unsigned a2 = f2tf32(r0hi.C);                                \
            const unsigned a3 = f2tf32(r1hi.C);                                \
            const int bb = base + I * (NNT * 32);                              \
            mma_tf32(d[0], a0, a1, a2, a3, b0sm[bb],      b1sm[bb]);           \
            mma_tf32(d[1], a0, a1, a2, a3, b0sm[bb + 32], b1sm[bb + 32]);      \
            mma_tf32(d[2], a0, a1, a2, a3, b0sm[bb + 64], b1sm[bb + 64]);      \
        } while (0)

        PSTEP(0, x);
        PSTEP(1, y);
        PSTEP(2, z);
        PSTEP(3, w);
#undef PSTEP
    }

#pragma unroll
    for (int nt = 0; nt < NNT; nt++) {
        const int col = nt * 8 + 2 * tig;
        csm[warp][gid][col]         = d[nt][0];
        csm[warp][gid][col + 1]     = d[nt][1];
        csm[warp][gid + 8][col]     = d[nt][2];
        csm[warp][gid + 8][col + 1] = d[nt][3];
    }
    __syncwarp();

    if (lane < 16) {
        const int q = qbase + lane;
        if (q < Q) {
            float p[NOUT];
#pragma unroll
            for (int j = 0; j < NOUT; j++) p[j] = csm[warp][lane][j];
#pragma unroll
            for (int j = 0; j < NOFF; j++) p[j] += __ldg(b_off + j);
#pragma unroll
            for (int j = 0; j < NAW; j++)  p[NOFF + j] += __ldg(b_attn + j);

            // fold reference points + grid transform into the coords:
            // ix = rx*W - 0.5 + ox ; iy = ry*H - 0.5 + oy
            {
                const int st = (__ldg(shapes_raw + 1) == 0) ? 2 : 1;
                const float* ref = refpts + (size_t)q * (LV * 2);
#pragma unroll
                for (int l = 0; l < LV; l++) {
                    const float Hf = (float)__ldg(shapes_raw + (2 * l) * st);
                    const float Wf = (float)__ldg(shapes_raw + (2 * l + 1) * st);
                    const float bx = __ldg(ref + 2 * l)     * Wf - 0.5f;
                    const float by = __ldg(ref + 2 * l + 1) * Hf - 0.5f;
#pragma unroll
                    for (int pt = 0; pt < NP; pt++) {
                        p[l * 8 + pt * 2]     += bx;
                        p[l * 8 + pt * 2 + 1] += by;
                    }
                }
            }

            float m = p[NOFF];
#pragma unroll
            for (int j = 1; j < NAW; j++) m = fmaxf(m, p[NOFF + j]);
            float s = 0.f;
#pragma unroll
            for (int j = 0; j < NAW; j++) {
                const float e = __expf(p[NOFF + j] - m);
                p[NOFF + j] = e;
                s += e;
            }
            const float inv = 1.f / s;
#pragma unroll
            for (int j = 0; j < NAW; j++) p[NOFF + j] *= inv;

            float4* o4 = (float4*)(g_P + (size_t)q * NOUT);
#pragma unroll
            for (int i = 0; i < 6; i++)
                o4[i] = make_float4(p[4 * i], p[4 * i + 1],
                                    p[4 * i + 2], p[4 * i + 3]);
        }
    }
}

// ---------------------------------------------------------------------------
// Kernel 2: bilinear sampling.  warp = query.
// Tent-weight merged-level dedup; pre-added coords from proj (no ref loads);
// gather loop 2 cells/iter (lower regs) at 6 blocks/SM.
// ---------------------------------------------------------------------------
__global__ __launch_bounds__(WPB * 32, 6)
void sample_kernel(const float* __restrict__ value,
                   const int*   __restrict__ shapes_raw,
                   float* __restrict__ out, int Q)
{
    const int tid  = threadIdx.x;
    const int lane = tid & 31;
    const int q = blockIdx.x * WPB + (tid >> 5);
    if (q >= Q) return;

    int HH[LV], WW[LV];
    {
        const int st = (__ldg(shapes_raw + 1) == 0) ? 2 : 1;
#pragma unroll
        for (int l = 0; l < LV; l++) {
            HH[l] = __ldg(shapes_raw + (2 * l) * st);
            WW[l] = __ldg(shapes_raw + (2 * l + 1) * st);
        }
    }

    const float4* pf  = (const float4*)(g_P + (size_t)q * NOUT);
    const float4* vb4 = (const float4*)value;

    float4 acc0 = make_float4(0.f, 0.f, 0.f, 0.f);
    float4 acc1 = make_float4(0.f, 0.f, 0.f, 0.f);

    float    myw   = 0.f;
    unsigned myoff = 0;
    const int mylevel = lane >> 4;
    const int mycell  = lane & 15;

    unsigned loff4 = 0;

#define GATHER_NOW(OFF4, W)                                                    \
    do {                                                                       \
        const float4 v0 = __ldg(vb4 + (OFF4) + lane);                          \
        const float4 v1 = __ldg(vb4 + (OFF4) + 32 + lane);                     \
        acc0.x = fmaf((W), v0.x, acc0.x);                                      \
        acc0.y = fmaf((W), v0.y, acc0.y);                                      \
        acc0.z = fmaf((W), v0.z, acc0.z);                                      \
        acc0.w = fmaf((W), v0.w, acc0.w);                                      \
        acc1.x = fmaf((W), v1.x, acc1.x);                                      \
        acc1.y = fmaf((W), v1.y, acc1.y);                                      \
        acc1.z = fmaf((W), v1.z, acc1.z);                                      \
        acc1.w = fmaf((W), v1.w, acc1.w);                                      \
    } while (0)

#pragma unroll
    for (int l = 0; l < LV; l++) {
        const int Hs = HH[l], Ws = WW[l];

        const float4 oA = __ldg(pf + 2 * l);       // ix/iy pts 0,1
        const float4 oB = __ldg(pf + 2 * l + 1);   // ix/iy pts 2,3
        const float4 wv = __ldg(pf + 4 + l);       // 4 normalized attn weights

        const float ixs[NP] = {oA.x, oA.z, oB.x, oB.z};
        const float iys[NP] = {oA.y, oA.w, oB.y, oB.w};
        const float aws[NP] = {wv.x, wv.y, wv.z, wv.w};

        int x0[NP], y0[NP];
#pragma unroll
        for (int pt = 0; pt < NP; pt++) {
            x0[pt] = (int)floorf(ixs[pt]);
            y0[pt] = (int)floorf(iys[pt]);
        }

        const int xmin = min(min(x0[0], x0[1]), min(x0[2], x0[3]));
        const int ymin = min(min(y0[0], y0[1]), min(y0[2], y0[3]));
        const int xmax = max(max(x0[0], x0[1]), max(x0[2], x0[3]));
        const int ymax = max(max(y0[0], y0[1]), max(y0[2], y0[3]));

        if (xmax - xmin <= 2 && ymax - ymin <= 2) {
            if (mylevel == l) {
                const int xx = xmin + (mycell & 3);
                const int yy = ymin + (mycell >> 2);
                const float Xc = (float)xx;
                const float Yc = (float)yy;
                float w = 0.f;
#pragma unroll
                for (int pt = 0; pt < NP; pt++) {
                    const float wx = fmaxf(0.f, 1.f - fabsf(ixs[pt] - Xc));
                    const float wy = fmaxf(0.f, 1.f - fabsf(iys[pt] - Yc));
                    w = fmaf(aws[pt] * wx, wy, w);
                }
                const bool ok = (unsigned)xx < (unsigned)Ws &&
                                (unsigned)yy < (unsigned)Hs;
                myw = ok ? w : 0.f;
                const int xc = min(max(xx, 0), Ws - 1);
                const int yc = min(max(yy, 0), Hs - 1);
                myoff = loff4 + (((unsigned)(yc * Ws + xc)) << 6);
            }
        } else {
            // Rare fallback: immediate per-corner gathers for this level.
#pragma unroll
            for (int pt = 0; pt < NP; pt++) {
                const float x0f = floorf(ixs[pt]);
                const float y0f = floorf(iys[pt]);
                const float fx = ixs[pt] - x0f;
                const float fy = iys[pt] - y0f;
                const float a  = aws[pt];
                const float cw[4] = {(1.f - fx) * (1.f - fy) * a,
                                     fx * (1.f - fy) * a,
                                     (1.f - fx) * fy * a,
                                     fx * fy * a};
                const int xs[2] = {x0[pt], x0[pt] + 1};
                const int ys[2] = {y0[pt], y0[pt] + 1};
#pragma unroll
                for (int cy = 0; cy < 2; cy++) {
#pragma unroll
                    for (int cx = 0; cx < 2; cx++) {
                        const int xx = xs[cx];
                        const int yy = ys[cy];
                        const float w = cw[cy * 2 + cx];
                        if ((unsigned)xx < (unsigned)Ws && (unsigned)yy < (unsigned)Hs) {
                            const unsigned off4 =
                                loff4 + (((unsigned)(yy * Ws + xx)) << 6);
                            GATHER_NOW(off4, w);
                        }
                    }
                }
            }
        }
        loff4 += (unsigned)(Hs * Ws) * 64u;
    }

    // Merged gather loop: 2 cells per iteration (lower register pressure).
    unsigned nz = __ballot_sync(0xffffffffu, myw != 0.f);
    while (nz) {
        int c0 = __ffs(nz) - 1; nz &= nz - 1;
        int c1 = __ffs(nz) - 1; nz &= nz - 1;

        float    w0 = __shfl_sync(0xffffffffu, myw,   c0 & 31);
        unsigned f0 = __shfl_sync(0xffffffffu, myoff, c0 & 31);
        float    w1 = __shfl_sync(0xffffffffu, myw,   c1 & 31);
        unsigned f1 = __shfl_sync(0xffffffffu, myoff, c1 & 31);
        if (c1 < 0) w1 = 0.f;

        float4 a1 = make_float4(0.f,0.f,0.f,0.f), b1 = a1;
        const float4 a0 = __ldg(vb4 + f0 + lane);
        const float4 b0 = __ldg(vb4 + f0 + 32 + lane);
        if (c1 >= 0) {
            a1 = __ldg(vb4 + f1 + lane);
            b1 = __ldg(vb4 + f1 + 32 + lane);
        }

        acc0.x = fmaf(w0, a0.x, acc0.x); acc0.y = fmaf(w0, a0.y, acc0.y);
        acc0.z = fmaf(w0, a0.z, acc0.z); acc0.w = fmaf(w0, a0.w, acc0.w);
        acc1.x = fmaf(w0, b0.x, acc1.x); acc1.y = fmaf(w0, b0.y, acc1.y);
        acc1.z = fmaf(w0, b0.z, acc1.z); acc1.w = fmaf(w0, b0.w, acc1.w);

        acc0.x = fmaf(w1, a1.x, acc0.x); acc0.y = fmaf(w1, a1.y, acc0.y);
        acc0.z = fmaf(w1, a1.z, acc0.z); acc0.w = fmaf(w1, a1.w, acc0.w);
        acc1.x = fmaf(w1, b1.x, acc1.x); acc1.y = fmaf(w1, b1.y, acc1.y);
        acc1.z = fmaf(w1, b1.z, acc1.z); acc1.w = fmaf(w1, b1.w, acc1.w);
    }
#undef GATHER_NOW

    float4* op = (float4*)(out + (size_t)q * CCH);
    op[lane]      = acc0;   // channels [4*lane, 4*lane+4)
    op[32 + lane] = acc1;   // channels [128+4*lane, ...)
}

extern "C" void kernel_launch(void* const* d_in, const int* in_sizes, int n_in,
                              void* d_out, int out_size)
{
    const float* query   = (const float*)d_in[0];
    // d_in[1] = key (unused)
    const float* value   = (const float*)d_in[2];
    const float* refpts  = (const float*)d_in[3];
    const int*   shapes  = (const int*)d_in[4];
    const float* W_off   = (const float*)d_in[5];
    const float* b_off   = (const float*)d_in[6];
    const float* W_attn  = (const float*)d_in[7];
    const float* b_attn  = (const float*)d_in[8];
    float*       out     = (float*)d_out;

    const int Q = in_sizes[0] / CCH;

    const int qpb = K1_WARPS * 16;
    proj_kernel<<<(Q + qpb - 1) / qpb, K1_WARPS * 32>>>(
        query, refpts, shapes, W_off, b_off, W_attn, b_attn, Q);
    sample_kernel<<<(Q + WPB - 1) / WPB, WPB * 32>>>(
        value, shapes, out, Q);
}

// round 15
// speedup vs baseline: 1.3851x; 1.0299x over previous
#include <cuda_runtime.h>
#include <cuda_bf16.h>

#define CCH 256        // channels
#define LV 2           // levels
#define NP 4           // points
#define NOFF 16        // offset outputs (LV*NP*2)
#define NAW 8          // attn outputs (LV*NP)
#define NOUT 24        // total projection outputs
#define WPB 8          // warps per block (sampling kernel)
#define NKT 32         // k-tiles (256 / 8)
#define NNT 3          // n-tiles (24 / 8)
#define K1_WARPS 8     // proj warps per block (128 queries/block)

// Scratch: per-query params {16 pre-added pixel coords, 8 normalized attn w}.
__device__ float g_P[1 << 21];   // 8.4 MB

__device__ __forceinline__ unsigned f2tf32(float f) {
    unsigned r;
    asm("cvt.rna.tf32.f32 %0, %1;" : "=r"(r) : "f"(f));
    return r;
}

__device__ __forceinline__ void mma_tf32(float d[4],
                                         unsigned a0, unsigned a1,
                                         unsigned a2, unsigned a3,
                                         unsigned b0, unsigned b1) {
    asm("mma.sync.aligned.m16n8k8.row.col.f32.tf32.tf32.f32 "
        "{%0,%1,%2,%3}, {%4,%5,%6,%7}, {%8,%9}, {%0,%1,%2,%3};"
        : "+f"(d[0]), "+f"(d[1]), "+f"(d[2]), "+f"(d[3])
        : "r"(a0), "r"(a1), "r"(a2), "r"(a3), "r"(b0), "r"(b1));
}

// ---------------------------------------------------------------------------
// Kernel 1: projection + softmax via tf32 MMA.
// 256-thread blocks (8 MMA warps) and 8-deep LDG batches (two k-groups per
// iteration) to double per-warp memory-level parallelism.
// Epilogue folds reference points: stores ix/iy pixel coords directly.
// ---------------------------------------------------------------------------
__global__ __launch_bounds__(K1_WARPS * 32)
void proj_kernel(const float* __restrict__ query,
                 const float* __restrict__ refpts,
                 const int*   __restrict__ shapes_raw,
                 const float* __restrict__ W_off,  const float* __restrict__ b_off,
                 const float* __restrict__ W_attn, const float* __restrict__ b_attn,
                 int Q)
{
    __shared__ unsigned b0sm[NKT * NNT * 32];         // 12KB
    __shared__ unsigned b1sm[NKT * NNT * 32];         // 12KB
    __shared__ float    csm[K1_WARPS][16][28];        // 14KB epilogue staging

    for (int idx = threadIdx.x; idx < NKT * NNT * 32; idx += K1_WARPS * 32) {
        const int ln   = idx & 31;
        const int pair = idx >> 5;
        const int kt   = pair / 3;
        const int nt   = pair - kt * 3;
        const int tig  = ln & 3;
        const int gid  = ln >> 2;
        const int n    = nt * 8 + gid;
        const int k0   = 32 * (kt >> 2) + 4 * tig + (kt & 3);
        const int k1   = k0 + 16;
        float w0, w1;
        if (n < NOFF) {
            w0 = __ldg(W_off + k0 * NOFF + n);
            w1 = __ldg(W_off + k1 * NOFF + n);
        } else {
            w0 = __ldg(W_attn + k0 * NAW + (n - NOFF));
            w1 = __ldg(W_attn + k1 * NAW + (n - NOFF));
        }
        b0sm[idx] = f2tf32(w0);
        b1sm[idx] = f2tf32(w1);
    }
    __syncthreads();

    const int tid  = threadIdx.x;
    const int lane = tid & 31;
    const int warp = tid >> 5;
    const int gid  = lane >> 2;
    const int tig  = lane & 3;

    const int qbase = blockIdx.x * (K1_WARPS * 16) + warp * 16;
    const int qr0 = min(qbase + gid,     Q - 1);
    const int qr1 = min(qbase + gid + 8, Q - 1);
    const float4* q0p = (const float4*)(query + (size_t)qr0 * CCH) + tig;
    const float4* q1p = (const float4*)(query + (size_t)qr1 * CCH) + tig;

    float d[NNT][4];
#pragma unroll
    for (int nt = 0; nt < NNT; nt++)
#pragma unroll
        for (int i = 0; i < 4; i++) d[nt][i] = 0.f;

#pragma unroll
    for (int kt8 = 0; kt8 < NKT / 8; kt8++) {
        // Two k-groups of loads (8 independent LDG.128), batched back-to-back.
        const float4 e0lo = __ldg(q0p + kt8 * 16);
        const float4 e0hi = __ldg(q0p + kt8 * 16 + 4);
        const float4 e1lo = __ldg(q1p + kt8 * 16);
        const float4 e1hi = __ldg(q1p + kt8 * 16 + 4);
        const float4 o0lo = __ldg(q0p + kt8 * 16 + 8);
        const float4 o0hi = __ldg(q0p + kt8 * 16 + 12);
        const float4 o1lo = __ldg(q1p + kt8 * 16 + 8);
        const float4 o1hi = __ldg(q1p + kt8 * 16 + 12);

        const int base_e = (kt8 * 8) * (NNT * 32) + lane;
        const int base_o = base_e + 4 * (NNT * 32);

#define PSTEP(BASE, R0LO, R0HI, R1LO, R1HI, I, C)                              \
        do {                                                                   \
            const unsigned a0 = f2tf32(R0LO.C);                                \
            const unsigned a1 = f2tf32(R1LO.C);                                \
            const unsigned a2 = f2tf32(R0HI.C);                                \
            const unsigned a3 = f2tf32(R1HI.C);                                \
            const int bb = (BASE) + I * (NNT * 32);                            \
            mma_tf32(d[0], a0, a1, a2, a3, b0sm[bb],      b1sm[bb]);           \
            mma_tf32(d[1], a0, a1, a2, a3, b0sm[bb + 32], b1sm[bb + 32]);      \
            mma_tf32(d[2], a0, a1, a2, a3, b0sm[bb + 64], b1sm[bb + 64]);      \
        } while (0)

        PSTEP(base_e, e0lo, e0hi, e1lo, e1hi, 0, x);
        PSTEP(base_e, e0lo, e0hi, e1lo, e1hi, 1, y);
        PSTEP(base_e, e0lo, e0hi, e1lo, e1hi, 2, z);
        PSTEP(base_e, e0lo, e0hi, e1lo, e1hi, 3, w);
        PSTEP(base_o, o0lo, o0hi, o1lo, o1hi, 0, x);
        PSTEP(base_o, o0lo, o0hi, o1lo, o1hi, 1, y);
        PSTEP(base_o, o0lo, o0hi, o1lo, o1hi, 2, z);
        PSTEP(base_o, o0lo, o0hi, o1lo, o1hi, 3, w);
#undef PSTEP
    }

#pragma unroll
    for (int nt = 0; nt < NNT; nt++) {
        const int col = nt * 8 + 2 * tig;
        csm[warp][gid][col]         = d[nt][0];
        csm[warp][gid][col + 1]     = d[nt][1];
        csm[warp][gid + 8][col]     = d[nt][2];
        csm[warp][gid + 8][col + 1] = d[nt][3];
    }
    __syncwarp();

    if (lane < 16) {
        const int q = qbase + lane;
        if (q < Q) {
            float p[NOUT];
#pragma unroll
            for (int j = 0; j < NOUT; j++) p[j] = csm[warp][lane][j];
#pragma unroll
            for (int j = 0; j < NOFF; j++) p[j] += __ldg(b_off + j);
#pragma unroll
            for (int j = 0; j < NAW; j++)  p[NOFF + j] += __ldg(b_attn + j);

            // fold reference points + grid transform into the coords:
            // ix = rx*W - 0.5 + ox ; iy = ry*H - 0.5 + oy
            {
                const int st = (__ldg(shapes_raw + 1) == 0) ? 2 : 1;
                const float* ref = refpts + (size_t)q * (LV * 2);
#pragma unroll
                for (int l = 0; l < LV; l++) {
                    const float Hf = (float)__ldg(shapes_raw + (2 * l) * st);
                    const float Wf = (float)__ldg(shapes_raw + (2 * l + 1) * st);
                    const float bx = __ldg(ref + 2 * l)     * Wf - 0.5f;
                    const float by = __ldg(ref + 2 * l + 1) * Hf - 0.5f;
#pragma unroll
                    for (int pt = 0; pt < NP; pt++) {
                        p[l * 8 + pt * 2]     += bx;
                        p[l * 8 + pt * 2 + 1] += by;
                    }
                }
            }

            float m = p[NOFF];
#pragma unroll
            for (int j = 1; j < NAW; j++) m = fmaxf(m, p[NOFF + j]);
            float s = 0.f;
#pragma unroll
            for (int j = 0; j < NAW; j++) {
                const float e = __expf(p[NOFF + j] - m);
                p[NOFF + j] = e;
                s += e;
            }
            const float inv = 1.f / s;
#pragma unroll
            for (int j = 0; j < NAW; j++) p[NOFF + j] *= inv;

            float4* o4 = (float4*)(g_P + (size_t)q * NOUT);
#pragma unroll
            for (int i = 0; i < 6; i++)
                o4[i] = make_float4(p[4 * i], p[4 * i + 1],
                                    p[4 * i + 2], p[4 * i + 3]);
        }
    }
}

// ---------------------------------------------------------------------------
// Kernel 2: bilinear sampling.  warp = query.  (unchanged — proven 41.6us)
// ---------------------------------------------------------------------------
__global__ __launch_bounds__(WPB * 32, 6)
void sample_kernel(const float* __restrict__ value,
                   const int*   __restrict__ shapes_raw,
                   float* __restrict__ out, int Q)
{
    const int tid  = threadIdx.x;
    const int lane = tid & 31;
    const int q = blockIdx.x * WPB + (tid >> 5);
    if (q >= Q) return;

    int HH[LV], WW[LV];
    {
        const int st = (__ldg(shapes_raw + 1) == 0) ? 2 : 1;
#pragma unroll
        for (int l = 0; l < LV; l++) {
            HH[l] = __ldg(shapes_raw + (2 * l) * st);
            WW[l] = __ldg(shapes_raw + (2 * l + 1) * st);
        }
    }

    const float4* pf  = (const float4*)(g_P + (size_t)q * NOUT);
    const float4* vb4 = (const float4*)value;

    float4 acc0 = make_float4(0.f, 0.f, 0.f, 0.f);
    float4 acc1 = make_float4(0.f, 0.f, 0.f, 0.f);

    float    myw   = 0.f;
    unsigned myoff = 0;
    const int mylevel = lane >> 4;
    const int mycell  = lane & 15;

    unsigned loff4 = 0;

#define GATHER_NOW(OFF4, W)                                                    \
    do {                                                                       \
        const float4 v0 = __ldg(vb4 + (OFF4) + lane);                          \
        const float4 v1 = __ldg(vb4 + (OFF4) + 32 + lane);                     \
        acc0.x = fmaf((W), v0.x, acc0.x);                                      \
        acc0.y = fmaf((W), v0.y, acc0.y);                                      \
        acc0.z = fmaf((W), v0.z, acc0.z);                                      \
        acc0.w = fmaf((W), v0.w, acc0.w);                                      \
        acc1.x = fmaf((W), v1.x, acc1.x);                                      \
        acc1.y = fmaf((W), v1.y, acc1.y);                                      \
        acc1.z = fmaf((W), v1.z, acc1.z);                                      \
        acc1.w = fmaf((W), v1.w, acc1.w);                                      \
    } while (0)

#pragma unroll
    for (int l = 0; l < LV; l++) {
        const int Hs = HH[l], Ws = WW[l];

        const float4 oA = __ldg(pf + 2 * l);       // ix/iy pts 0,1
        const float4 oB = __ldg(pf + 2 * l + 1);   // ix/iy pts 2,3
        const float4 wv = __ldg(pf + 4 + l);       // 4 normalized attn weights

        const float ixs[NP] = {oA.x, oA.z, oB.x, oB.z};
        const float iys[NP] = {oA.y, oA.w, oB.y, oB.w};
        const float aws[NP] = {wv.x, wv.y, wv.z, wv.w};

        int x0[NP], y0[NP];
#pragma unroll
        for (int pt = 0; pt < NP; pt++) {
            x0[pt] = (int)floorf(ixs[pt]);
            y0[pt] = (int)floorf(iys[pt]);
        }

        const int xmin = min(min(x0[0], x0[1]), min(x0[2], x0[3]));
        const int ymin = min(min(y0[0], y0[1]), min(y0[2], y0[3]));
        const int xmax = max(max(x0[0], x0[1]), max(x0[2], x0[3]));
        const int ymax = max(max(y0[0], y0[1]), max(y0[2], y0[3]));

        if (xmax - xmin <= 2 && ymax - ymin <= 2) {
            if (mylevel == l) {
                const int xx = xmin + (mycell & 3);
                const int yy = ymin + (mycell >> 2);
                const float Xc = (float)xx;
                const float Yc = (float)yy;
                float w = 0.f;
#pragma unroll
                for (int pt = 0; pt < NP; pt++) {
                    const float wx = fmaxf(0.f, 1.f - fabsf(ixs[pt] - Xc));
                    const float wy = fmaxf(0.f, 1.f - fabsf(iys[pt] - Yc));
                    w = fmaf(aws[pt] * wx, wy, w);
                }
                const bool ok = (unsigned)xx < (unsigned)Ws &&
                                (unsigned)yy < (unsigned)Hs;
                myw = ok ? w : 0.f;
                const int xc = min(max(xx, 0), Ws - 1);
                const int yc = min(max(yy, 0), Hs - 1);
                myoff = loff4 + (((unsigned)(yc * Ws + xc)) << 6);
            }
        } else {
            // Rare fallback: immediate per-corner gathers for this level.
#pragma unroll
            for (int pt = 0; pt < NP; pt++) {
                const float x0f = floorf(ixs[pt]);
                const float y0f = floorf(iys[pt]);
                const float fx = ixs[pt] - x0f;
                const float fy = iys[pt] - y0f;
                const float a  = aws[pt];
                const float cw[4] = {(1.f - fx) * (1.f - fy) * a,
                                     fx * (1.f - fy) * a,
                                     (1.f - fx) * fy * a,
                                     fx * fy * a};
                const int xs[2] = {x0[pt], x0[pt] + 1};
                const int ys[2] = {y0[pt], y0[pt] + 1};
#pragma unroll
                for (int cy = 0; cy < 2; cy++) {
#pragma unroll
                    for (int cx = 0; cx < 2; cx++) {
                        const int xx = xs[cx];
                        const int yy = ys[cy];
                        const float w = cw[cy * 2 + cx];
                        if ((unsigned)xx < (unsigned)Ws && (unsigned)yy < (unsigned)Hs) {
                            const unsigned off4 =
                                loff4 + (((unsigned)(yy * Ws + xx)) << 6);
                            GATHER_NOW(off4, w);
                        }
                    }
                }
            }
        }
        loff4 += (unsigned)(Hs * Ws) * 64u;
    }

    // Merged gather loop: 2 cells per iteration.
    unsigned nz = __ballot_sync(0xffffffffu, myw != 0.f);
    while (nz) {
        int c0 = __ffs(nz) - 1; nz &= nz - 1;
        int c1 = __ffs(nz) - 1; nz &= nz - 1;

        float    w0 = __shfl_sync(0xffffffffu, myw,   c0 & 31);
        unsigned f0 = __shfl_sync(0xffffffffu, myoff, c0 & 31);
        float    w1 = __shfl_sync(0xffffffffu, myw,   c1 & 31);
        unsigned f1 = __shfl_sync(0xffffffffu, myoff, c1 & 31);
        if (c1 < 0) w1 = 0.f;

        float4 a1 = make_float4(0.f,0.f,0.f,0.f), b1 = a1;
        const float4 a0 = __ldg(vb4 + f0 + lane);
        const float4 b0 = __ldg(vb4 + f0 + 32 + lane);
        if (c1 >= 0) {
            a1 = __ldg(vb4 + f1 + lane);
            b1 = __ldg(vb4 + f1 + 32 + lane);
        }

        acc0.x = fmaf(w0, a0.x, acc0.x); acc0.y = fmaf(w0, a0.y, acc0.y);
        acc0.z = fmaf(w0, a0.z, acc0.z); acc0.w = fmaf(w0, a0.w, acc0.w);
        acc1.x = fmaf(w0, b0.x, acc1.x); acc1.y = fmaf(w0, b0.y, acc1.y);
        acc1.z = fmaf(w0, b0.z, acc1.z); acc1.w = fmaf(w0, b0.w, acc1.w);

        acc0.x = fmaf(w1, a1.x, acc0.x); acc0.y = fmaf(w1, a1.y, acc0.y);
        acc0.z = fmaf(w1, a1.z, acc0.z); acc0.w = fmaf(w1, a1.w, acc0.w);
        acc1.x = fmaf(w1, b1.x, acc1.x); acc1.y = fmaf(w1, b1.y, acc1.y);
        acc1.z = fmaf(w1, b1.z, acc1.z); acc1.w = fmaf(w1, b1.w, acc1.w);
    }
#undef GATHER_NOW

    float4* op = (float4*)(out + (size_t)q * CCH);
    op[lane]      = acc0;   // channels [4*lane, 4*lane+4)
    op[32 + lane] = acc1;   // channels [128+4*lane, ...)
}

extern "C" void kernel_launch(void* const* d_in, const int* in_sizes, int n_in,
                              void* d_out, int out_size)
{
    const float* query   = (const float*)d_in[0];
    // d_in[1] = key (unused)
    const float* value   = (const float*)d_in[2];
    const float* refpts  = (const float*)d_in[3];
    const int*   shapes  = (const int*)d_in[4];
    const float* W_off   = (const float*)d_in[5];
    const float* b_off   = (const float*)d_in[6];
    const float* W_attn  = (const float*)d_in[7];
    const float* b_attn  = (const float*)d_in[8];
    float*       out     = (float*)d_out;

    const int Q = in_sizes[0] / CCH;

    const int qpb = K1_WARPS * 16;
    proj_kernel<<<(Q + qpb - 1) / qpb, K1_WARPS * 32>>>(
        query, refpts, shapes, W_off, b_off, W_attn, b_attn, Q);
    sample_kernel<<<(Q + WPB - 1) / WPB, WPB * 32>>>(
        value, shapes, out, Q);
}